// round 9
// baseline (speedup 1.0000x reference)
#include <cuda_runtime.h>
#include <cuda_bf16.h>
#include <cstdint>

// Locally-connected conv via mma.sync bf16 split precision (arch-generic HMMA).
// Per (h,w): D[o=64, b=32] = W[o,288] X[288,b] + bias.
// smem B tile = [n=64][k] bf16: rows 0-31 Xh, rows 32-63 Xl.
// Pass structure per k-step: Ah x (Xh|Xl) [8 mma] + Al x Xh [4 mma].
// Out = WhXh + WhXl + WlXh (+bias); dropped WlXl ~ 2^-17.

#define B_    32
#define CIN_  32
#define IH_   64
#define IW_   64
#define COUT_ 64
#define OH_   64
#define OW_   64
#define KTOT  288
#define KROW  296            // smem row stride (bf16 elems) = 592 B, LDSM conflict-free
#define NSTEP 18             // KTOT / 16

__device__ __forceinline__ uint32_t prmt_hi(uint32_t a, uint32_t b) {
    uint32_t r; asm("prmt.b32 %0, %1, %2, 0x7632;" : "=r"(r) : "r"(a), "r"(b)); return r;
}
__device__ __forceinline__ uint32_t hi_pack(float2 f) {
    return prmt_hi(__float_as_uint(f.x), __float_as_uint(f.y));
}
__device__ __forceinline__ uint32_t lo_pack(float2 f) {
    float h0 = __uint_as_float(__float_as_uint(f.x) & 0xFFFF0000u);
    float h1 = __uint_as_float(__float_as_uint(f.y) & 0xFFFF0000u);
    __nv_bfloat162 p = __floats2bfloat162_rn(f.x - h0, f.y - h1);  // .x in low 16
    return reinterpret_cast<uint32_t&>(p);
}
__device__ __forceinline__ void ldsm4(uint32_t& r0, uint32_t& r1, uint32_t& r2, uint32_t& r3,
                                      uint32_t a) {
    asm volatile("ldmatrix.sync.aligned.m8n8.x4.shared.b16 {%0,%1,%2,%3}, [%4];"
                 : "=r"(r0), "=r"(r1), "=r"(r2), "=r"(r3) : "r"(a));
}
__device__ __forceinline__ void mma16816(float* c,
                                         uint32_t a0, uint32_t a1, uint32_t a2, uint32_t a3,
                                         uint32_t b0, uint32_t b1) {
    asm volatile("mma.sync.aligned.m16n8k16.row.col.f32.bf16.bf16.f32 "
                 "{%0,%1,%2,%3}, {%4,%5,%6,%7}, {%8,%9}, {%0,%1,%2,%3};"
                 : "+f"(c[0]), "+f"(c[1]), "+f"(c[2]), "+f"(c[3])
                 : "r"(a0), "r"(a1), "r"(a2), "r"(a3), "r"(b0), "r"(b1));
}

__global__ __launch_bounds__(128, 4)
void lc_conv_mma(const float* __restrict__ x, const float* __restrict__ wgt,
                 const float* __restrict__ bias, float* __restrict__ out)
{
    __shared__ __align__(16) __nv_bfloat16 xs[64][KROW];   // 37888 B

    const int w    = blockIdx.x, h = blockIdx.y;
    const int t    = threadIdx.x;
    const int wid  = t >> 5, lane = t & 31;
    const int gid  = lane >> 2;        // 0..7
    const int tig  = lane & 3;         // 0..3

    // ---------------- stage X (hi/lo bf16) into smem ----------------
    for (int u = t; u < B_ * CIN_ * 3; u += 128) {
        int b  = u & 31;
        int ci = u >> 5;
        int c  = ci / 3, i = ci - 3 * c;
        int row = h + i - 1;
        int k0  = c * 9 + i * 3;
        float v[3] = {0.f, 0.f, 0.f};
        if ((unsigned)row < IH_) {
            const float* xp = x + (((size_t)b * CIN_ + c) * IH_ + row) * IW_ + (w - 1);
#pragma unroll
            for (int j = 0; j < 3; j++)
                if ((unsigned)(w - 1 + j) < IW_) v[j] = xp[j];
        }
#pragma unroll
        for (int j = 0; j < 3; j++) {
            uint32_t ub = __float_as_uint(v[j]);
            unsigned short hs = (unsigned short)(ub >> 16);            // truncate-hi
            float hf = __uint_as_float(ub & 0xFFFF0000u);
            __nv_bfloat16 lo = __float2bfloat16(v[j] - hf);            // rn-lo
            xs[b][k0 + j]      = reinterpret_cast<__nv_bfloat16&>(hs);
            xs[b + 32][k0 + j] = lo;
        }
    }
    __syncthreads();

    // ---------------- per-warp GEMM ----------------
    // warp wid handles output rows o in [16*wid, 16*wid+16)
    const int o0 = wid * 16;
    const float* wp = wgt + (((size_t)(h * OW_ + w) * COUT_) + o0 + gid) * KTOT + 2 * tig;
    const float* wp8 = wp + 8 * KTOT;

    // LDSM base addresses for the 4 jp groups (covering n-tiles 2jp, 2jp+1)
    uint32_t lds_addr[4];
    {
        uint32_t base = (uint32_t)__cvta_generic_to_shared(&xs[0][0]);
        int nrow = 8 * ((lane >> 4) & 1) + (lane & 7);
        int kadd = 8 * ((lane >> 3) & 1);
#pragma unroll
        for (int jp = 0; jp < 4; jp++)
            lds_addr[jp] = base + (uint32_t)(16 * jp + nrow) * (KROW * 2) + kadd * 2;
    }

    float acc1[8][4];   // Wh x n-tiles 0..7  (Xh | Xl)
    float acc2[4][4];   // Wl x n-tiles 0..3  (Xh)
#pragma unroll
    for (int j = 0; j < 8; j++)
#pragma unroll
        for (int q = 0; q < 4; q++) acc1[j][q] = 0.f;
#pragma unroll
    for (int j = 0; j < 4; j++)
#pragma unroll
        for (int q = 0; q < 4; q++) acc2[j][q] = 0.f;

    // prefetch W for step 0
    float2 cw0 = *(const float2*)(wp);
    float2 cw1 = *(const float2*)(wp + 8);
    float2 cw2 = *(const float2*)(wp8);
    float2 cw3 = *(const float2*)(wp8 + 8);

#pragma unroll 1
    for (int step = 0; step < NSTEP; step++) {
        // convert current W regs -> A fragments
        uint32_t ah0 = hi_pack(cw0), ah2 = hi_pack(cw1);
        uint32_t ah1 = hi_pack(cw2), ah3 = hi_pack(cw3);
        uint32_t al0 = lo_pack(cw0), al2 = lo_pack(cw1);
        uint32_t al1 = lo_pack(cw2), al3 = lo_pack(cw3);

        // prefetch next step's W
        if (step + 1 < NSTEP) {
            int kn = (step + 1) * 16;
            cw0 = *(const float2*)(wp + kn);
            cw1 = *(const float2*)(wp + kn + 8);
            cw2 = *(const float2*)(wp8 + kn);
            cw3 = *(const float2*)(wp8 + kn + 8);
        }

        // B fragments for this k-step
        uint32_t bb[16];
        uint32_t koff = (uint32_t)step * 32;   // 16 bf16 = 32 B
#pragma unroll
        for (int jp = 0; jp < 4; jp++)
            ldsm4(bb[4 * jp], bb[4 * jp + 1], bb[4 * jp + 2], bb[4 * jp + 3],
                  lds_addr[jp] + koff);
        // bb layout: [4jp]=b0(ntile 2jp), [4jp+1]=b1(2jp), [4jp+2]=b0(2jp+1), [4jp+3]=b1(2jp+1)

#pragma unroll
        for (int j = 0; j < 8; j++) {
            uint32_t b0 = bb[(j >> 1) * 4 + (j & 1) * 2];
            uint32_t b1 = bb[(j >> 1) * 4 + (j & 1) * 2 + 1];
            mma16816(acc1[j], ah0, ah1, ah2, ah3, b0, b1);
        }
#pragma unroll
        for (int j = 0; j < 4; j++) {
            uint32_t b0 = bb[(j >> 1) * 4 + (j & 1) * 2];
            uint32_t b1 = bb[(j >> 1) * 4 + (j & 1) * 2 + 1];
            mma16816(acc2[j], al0, al1, al2, al3, b0, b1);
        }
    }

    // ---------------- epilogue: combine products + bias, store ----------------
    const int o_lo = o0 + gid;
    const int o_hi = o_lo + 8;
    const float bias_lo = bias[(o_lo * OH_ + h) * OW_ + w];
    const float bias_hi = bias[(o_hi * OH_ + h) * OW_ + w];

#pragma unroll
    for (int j = 0; j < 4; j++) {
        int b = 8 * j + 2 * tig;
        float v00 = acc1[j][0] + acc1[j + 4][0] + acc2[j][0] + bias_lo;  // (o_lo, b)
        float v01 = acc1[j][1] + acc1[j + 4][1] + acc2[j][1] + bias_lo;  // (o_lo, b+1)
        float v10 = acc1[j][2] + acc1[j + 4][2] + acc2[j][2] + bias_hi;  // (o_hi, b)
        float v11 = acc1[j][3] + acc1[j + 4][3] + acc2[j][3] + bias_hi;  // (o_hi, b+1)
        size_t p00 = (((size_t)b * COUT_ + o_lo) * OH_ + h) * OW_ + w;
        size_t p01 = (((size_t)(b + 1) * COUT_ + o_lo) * OH_ + h) * OW_ + w;
        out[p00] = v00;
        out[p01] = v01;
        out[p00 + (size_t)8 * OH_ * OW_] = v10;   // o_hi = o_lo + 8
        out[p01 + (size_t)8 * OH_ * OW_] = v11;
    }
}

extern "C" void kernel_launch(void* const* d_in, const int* in_sizes, int n_in,
                              void* d_out, int out_size)
{
    const float* x    = (const float*)d_in[0];   // [32,32,64,64]
    const float* wgt  = (const float*)d_in[1];   // [64,64,64,32,3,3]
    const float* bias = (const float*)d_in[2];   // [64,64,64]
    float* out = (float*)d_out;                  // [32,64,64,64]

    dim3 grid(OW_, OH_);
    lc_conv_mma<<<grid, 128>>>(x, wgt, bias, out);
}